// round 16
// baseline (speedup 1.0000x reference)
#include <cuda_runtime.h>
#include <cuda_fp16.h>
#include <math.h>
#include <stdint.h>

#define B 64
#define S 2048
#define E 1024
#define H 512
#define EMBD 256
#define V 50257
#define MTOT (B*S)
#define NLBLK ((V + 127)/128)      // 393 logits CTAs

#define OUT_HT ((size_t)B*V)
#define OUT_CT (OUT_HT + (size_t)B*H)

// ---------------- device scratch (no allocations allowed) ----------------
__device__ float g_ws_app[B*H];
__device__ float g_energy4[4][MTOT];
__device__ float g_attn[MTOT];
__device__ float g_context[B*E];
__device__ float g_embed[B*EMBD];
__device__ float g_gates8[8][B*4*H];
__device__ float g_logits[(size_t)B*V];
__device__ float g_pgen[B];
__device__ float g_lmax[NLBLK][B];
__device__ float g_lsum[NLBLK][B];
__device__ float g_vfin[B*2];

__device__ __half g_w_h[H*E];          // attn_wh_w fp16
__device__ __half g_ht_hi[B*H];
__device__ __half g_ht_lo[B*H];

__device__ __forceinline__ float sigf(float x){ return 1.f/(1.f+__expf(-x)); }
__device__ __forceinline__ float ftanh(float x){
    x = fminf(fmaxf(x, -15.f), 15.f);
    float e2 = __expf(2.f*x);
    return (e2 - 1.f) / (e2 + 1.f);
}
__device__ __forceinline__ void online(float& m, float& s, float x){
    if (x > m){ s = s*__expf(m - x) + 1.f; m = x; }
    else        s += __expf(x - m);
}
__device__ __forceinline__ void online_merge(float& m, float& s, float mo, float so){
    float M = fmaxf(m, mo);
    s = s*__expf(m - M) + so*__expf(mo - M);
    m = M;
}

// ======================= portable PTX helpers =============================
__device__ __forceinline__ uint32_t smem_u32(const void* p){
    uint32_t a;
    asm("{ .reg .u64 t; cvta.to.shared.u64 t, %1; cvt.u32.u64 %0, t; }" : "=r"(a) : "l"(p));
    return a;
}
__device__ __forceinline__ void cp16(uint32_t dst, const void* src){
    asm volatile("cp.async.cg.shared.global [%0], [%1], 16;" :: "r"(dst), "l"(src));
}
__device__ __forceinline__ void cp_commit(){ asm volatile("cp.async.commit_group;" ::: "memory"); }
__device__ __forceinline__ void cp_wait0(){ asm volatile("cp.async.wait_group 0;" ::: "memory"); }

__device__ __forceinline__ void ldsm4(uint32_t* r, uint32_t addr){
    asm volatile("ldmatrix.sync.aligned.m8n8.x4.shared.b16 {%0,%1,%2,%3}, [%4];"
        : "=r"(r[0]), "=r"(r[1]), "=r"(r[2]), "=r"(r[3]) : "r"(addr));
}
__device__ __forceinline__ void mma_f16(float* c, const uint32_t* a, uint32_t b0, uint32_t b1){
    asm volatile("mma.sync.aligned.m16n8k16.row.col.f32.f16.f16.f32 "
        "{%0,%1,%2,%3}, {%4,%5,%6,%7}, {%8,%9}, {%0,%1,%2,%3};"
        : "+f"(c[0]), "+f"(c[1]), "+f"(c[2]), "+f"(c[3])
        : "r"(a[0]), "r"(a[1]), "r"(a[2]), "r"(a[3]), "r"(b0), "r"(b1));
}

// ---------------- fp16 conversion for attn weights ------------------------
__global__ void conv_w_kernel(const float* __restrict__ src){
    int i = blockIdx.x*256 + threadIdx.x;
    g_w_h[i] = __float2half(src[i]);
}

// ---------------- init: zero context + embedding lookup ------------------
__global__ void init_kernel(const int* __restrict__ dec_input,
                            const float* __restrict__ table){
    int i = blockIdx.x*256 + threadIdx.x;
    if (i < B*E) g_context[i] = 0.f;
    if (i < B*EMBD){
        int b = i >> 8, t = i & 255;
        g_embed[i] = table[(size_t)dec_input[b]*EMBD + t];
    }
}

// ---------------- ws_app ---------------------------------------------------
__global__ void wsapp_kernel(const float* __restrict__ h0,
                             const float* __restrict__ ws_w,
                             const float* __restrict__ ws_b,
                             const float* __restrict__ wh_b){
    __shared__ float hs[H];
    const int b = blockIdx.x, tid = threadIdx.x;
    for (int i = tid; i < H; i += 256) hs[i] = h0[b*H + i];
    __syncthreads();
    const int warp = tid >> 5, lane = tid & 31;
    const int n = blockIdx.y * 8 + warp;
    const float* wrow = ws_w + (size_t)n*H;
    float acc = 0.f;
    #pragma unroll
    for (int k = lane*4; k < H; k += 128){
        float4 w = *(const float4*)(wrow + k);
        acc += hs[k]*w.x + hs[k+1]*w.y + hs[k+2]*w.z + hs[k+3]*w.w;
    }
    #pragma unroll
    for (int o = 16; o > 0; o >>= 1) acc += __shfl_xor_sync(0xffffffffu, acc, o);
    if (lane == 0) g_ws_app[b*H + n] = acc + ws_b[n] + wh_b[n];
}

// ---------------- energy GEMM: A direct-to-fragment, B via smem ----------
// A (enc) fp32 LDG in mma-fragment layout, hi/lo split in-register.
#define MT 128
#define NTILE 128
#define KC 32
#define NCH (E/KC)
#define ROWB 80
#define ARRB (128*ROWB)            // 10240 (one B stage)
#define WS_OFF (2*ARRB)            // 20480
#define V_OFF  (WS_OFF + 512)
#define EN_SMEM (V_OFF + 512)      // 21504

__global__ __launch_bounds__(256, 2) void energy_mma(
        const float* __restrict__ enc, const float* __restrict__ attn_v){
    extern __shared__ char sm[];
    const int tid  = threadIdx.x;
    const int lane = tid & 31, wid = tid >> 5;
    const int wm = wid & 3;
    const int wn = wid >> 2;
    const int n0 = blockIdx.x * NTILE;
    const int m0 = blockIdx.y * MT;
    const int b  = m0 >> 11;

    float* wsP = (float*)(sm + WS_OFF);
    float* vP  = (float*)(sm + V_OFF);
    for (int j = tid; j < NTILE; j += 256){
        wsP[j] = g_ws_app[b*H + n0 + j];
        vP[j]  = attn_v[n0 + j];
    }

    const uint32_t smb = smem_u32(sm);
    const __half* Bg = g_w_h + (size_t)n0*E;

    auto loadB = [&](int stage, int k0){
        uint32_t stg = smb + (stage&1)*ARRB;
        #pragma unroll
        for (int it = 0; it < 2; it++){
            int f = tid + it*256;
            int r = f >> 2, j = f & 3;
            cp16(stg + r*ROWB + j*16, Bg + (size_t)r*E + k0 + j*8);
        }
        cp_commit();
    };

    // A fragment base: lane owns row fr, k-pair fk (mma m16n8k16 A layout)
    const int fr = lane >> 2;
    const int fk = (lane & 3)*2;
    const float* Af = enc + (size_t)(m0 + wm*32 + fr)*E + fk;

    float c[2][8][4];
    #pragma unroll
    for (int t = 0; t < 2; t++)
        #pragma unroll
        for (int j = 0; j < 8; j++)
            #pragma unroll
            for (int q = 0; q < 4; q++) c[t][j][q] = 0.f;

    loadB(0, 0);

    for (int i = 0; i < NCH; i++){
        cp_wait0();
        __syncthreads();                 // B(i) visible; MMA(i-1) retired
        if (i + 1 < NCH) loadB(i+1, (i+1)*KC);

        const uint32_t B0 = smb + (i&1)*ARRB;
        const int kb = i*KC;

        // A fragments for both k16 halves, direct from global (L2-hot)
        uint32_t ahi[2][2][4], alo[2][2][4];    // [kk][t][j]
        #pragma unroll
        for (int kk = 0; kk < 2; kk++)
            #pragma unroll
            for (int t = 0; t < 2; t++)
                #pragma unroll
                for (int j = 0; j < 4; j++){
                    const float2 v = *(const float2*)(Af
                        + (size_t)(t*16 + (j&1)*8)*E + (j>>1)*8 + kb + kk*16);
                    __half hx = __float2half(v.x), hy = __float2half(v.y);
                    __half lx = __float2half(v.x - __half2float(hx));
                    __half ly = __float2half(v.y - __half2float(hy));
                    ahi[kk][t][j] = ((uint32_t)__half_as_ushort(hy) << 16) | __half_as_ushort(hx);
                    alo[kk][t][j] = ((uint32_t)__half_as_ushort(ly) << 16) | __half_as_ushort(lx);
                }

        #pragma unroll
        for (int kk = 0; kk < 2; kk++){
            #pragma unroll
            for (int p = 0; p < 4; p++){
                int row = wn*64 + p*16 + ((lane >> 4) & 1)*8 + (lane & 7);
                uint32_t off = (uint32_t)row*ROWB + ((lane >> 3) & 1)*16 + kk*32;
                uint32_t rh[4];
                ldsm4(rh, B0 + off);
                #pragma unroll
                for (int t = 0; t < 2; t++){
                    mma_f16(c[t][2*p],   ahi[kk][t], rh[0], rh[1]);
                    mma_f16(c[t][2*p],   alo[kk][t], rh[0], rh[1]);
                    mma_f16(c[t][2*p+1], ahi[kk][t], rh[2], rh[3]);
                    mma_f16(c[t][2*p+1], alo[kk][t], rh[2], rh[3]);
                }
            }
        }
    }

    float p4[4] = {0.f, 0.f, 0.f, 0.f};
    #pragma unroll
    for (int t = 0; t < 2; t++)
        #pragma unroll
        for (int j = 0; j < 8; j++)
            #pragma unroll
            for (int q = 0; q < 4; q++){
                int nloc = wn*64 + j*8 + (lane & 3)*2 + (q & 1);
                float x = c[t][j][q] + wsP[nloc];
                p4[t*2 + (q >> 1)] += ftanh(x) * vP[nloc];
            }
    #pragma unroll
    for (int q = 0; q < 4; q++){
        p4[q] += __shfl_xor_sync(0xffffffffu, p4[q], 1);
        p4[q] += __shfl_xor_sync(0xffffffffu, p4[q], 2);
    }
    __syncthreads();
    float* red = (float*)(sm);
    if ((lane & 3) == 0){
        int rloc = wm*32 + (lane >> 2);
        if (wn == 0){
            red[rloc]      = p4[0];
            red[rloc + 8]  = p4[1];
            red[rloc + 16] = p4[2];
            red[rloc + 24] = p4[3];
        }
    }
    __syncthreads();
    if (wn == 1 && (lane & 3) == 0){
        int rloc = wm*32 + (lane >> 2);
        g_energy4[blockIdx.x][m0 + rloc]      = red[rloc]      + p4[0];
        g_energy4[blockIdx.x][m0 + rloc + 8]  = red[rloc + 8]  + p4[1];
        g_energy4[blockIdx.x][m0 + rloc + 16] = red[rloc + 16] + p4[2];
        g_energy4[blockIdx.x][m0 + rloc + 24] = red[rloc + 24] + p4[3];
    }
}

// ---------------- softmax over S per batch -------------------------------
__global__ void attn_softmax(){
    const int b = blockIdx.x, t = threadIdx.x;
    __shared__ float red[8];
    float ev[8];
    float m = -1e30f;
    #pragma unroll
    for (int q = 0; q < 8; q++){
        int idx = b*S + q*256 + t;
        float v = g_energy4[0][idx] + g_energy4[1][idx] + g_energy4[2][idx] + g_energy4[3][idx];
        ev[q] = v;
        m = fmaxf(m, v);
    }
    #pragma unroll
    for (int o = 16; o > 0; o >>= 1) m = fmaxf(m, __shfl_xor_sync(0xffffffffu, m, o));
    if ((t & 31) == 0) red[t >> 5] = m;
    __syncthreads();
    if (t == 0){ float mm = red[0]; for (int i = 1; i < 8; i++) mm = fmaxf(mm, red[i]); red[0] = mm; }
    __syncthreads();
    m = red[0];
    __syncthreads();
    float s = 0.f;
    #pragma unroll
    for (int q = 0; q < 8; q++){ ev[q] = __expf(ev[q]-m); s += ev[q]; }
    #pragma unroll
    for (int o = 16; o > 0; o >>= 1) s += __shfl_xor_sync(0xffffffffu, s, o);
    if ((t & 31) == 0) red[t >> 5] = s;
    __syncthreads();
    if (t == 0){ float ss = 0.f; for (int i = 0; i < 8; i++) ss += red[i]; red[0] = ss; }
    __syncthreads();
    float inv = 1.f / red[0];
    #pragma unroll
    for (int q = 0; q < 8; q++) g_attn[b*S + q*256 + t] = ev[q] * inv;
}

// ---------------- context --------------------------------------------------
__global__ void context_kernel(const float* __restrict__ enc){
    const int b = blockIdx.x, ec = blockIdx.y, sc = blockIdx.z;
    __shared__ float a_s[512];
    const int t = threadIdx.x;
    for (int i = t; i < 512; i += 256) a_s[i] = g_attn[b*S + sc*512 + i];
    __syncthreads();
    const int e = ec*256 + t;
    const float* base = enc + ((size_t)b*S + sc*512)*E + e;
    float acc = 0.f;
    #pragma unroll 4
    for (int s = 0; s < 512; s++) acc = fmaf(a_s[s], base[(size_t)s*E], acc);
    atomicAdd(&g_context[b*E + e], acc);
}

// ---------------- LSTM gates GEMM (K-split x8) ---------------------------
__global__ __launch_bounds__(256) void gates_gemm(
        const float* __restrict__ h0,
        const float* __restrict__ w_ih,
        const float* __restrict__ w_hh){
    __shared__ float Xs[16][65];
    __shared__ float Ws[16][65];
    const int n0 = blockIdx.x * 64;
    const int ks = blockIdx.y;
    const int tid = threadIdx.x;
    const int tx = tid & 15, ty = tid >> 4;
    float acc[4][4];
    #pragma unroll
    for (int i = 0; i < 4; i++)
        #pragma unroll
        for (int j = 0; j < 4; j++) acc[i][j] = 0.f;

    for (int k0 = ks*224; k0 < (ks+1)*224; k0 += 16) {
        for (int i = tid; i < 64*16; i += 256){
            int m = i >> 4, kk = i & 15, k = k0 + kk;
            float xv;
            if (k < E)            xv = g_context[m*E + k];
            else if (k < E+EMBD)  xv = g_embed[m*EMBD + (k - E)];
            else                  xv = h0[m*H + (k - E - EMBD)];
            Xs[kk][m] = xv;
        }
        for (int i = tid; i < 64*16; i += 256){
            int nn = i >> 4, kk = i & 15, k = k0 + kk, n = n0 + nn;
            float wv = (k < E+EMBD) ? w_ih[(size_t)n*(E+EMBD) + k]
                                    : w_hh[(size_t)n*H + (k - E - EMBD)];
            Ws[kk][nn] = wv;
        }
        __syncthreads();
        #pragma unroll
        for (int kk = 0; kk < 16; kk++){
            float ra[4], rb[4];
            #pragma unroll
            for (int i = 0; i < 4; i++) ra[i] = Xs[kk][ty*4+i];
            #pragma unroll
            for (int j = 0; j < 4; j++) rb[j] = Ws[kk][tx*4+j];
            #pragma unroll
            for (int i = 0; i < 4; i++)
                #pragma unroll
                for (int j = 0; j < 4; j++) acc[i][j] = fmaf(ra[i], rb[j], acc[i][j]);
        }
        __syncthreads();
    }
    #pragma unroll
    for (int i = 0; i < 4; i++)
        #pragma unroll
        for (int j = 0; j < 4; j++){
            int m = ty*4+i, n = n0 + tx*4+j;
            g_gates8[ks][m*(4*H) + n] = acc[i][j];
        }
}

// ---------------- LSTM pointwise + p_gen (fused) -------------------------
__global__ void lstm_kernel(const float* __restrict__ c0,
                            const float* __restrict__ b_ih,
                            const float* __restrict__ b_hh,
                            const float* __restrict__ wh_vec,
                            const float* __restrict__ ws_vec,
                            const float* __restrict__ wx_vec,
                            float* __restrict__ out){
    __shared__ float red[16];
    const int b = blockIdx.x, h = threadIdx.x;
    const int base = b*(4*H);
    float gi = 0.f, gf = 0.f, gg = 0.f, go = 0.f;
    #pragma unroll
    for (int p = 0; p < 8; p++){
        const float* gp = g_gates8[p] + base;
        gi += gp[h];
        gf += gp[H + h];
        gg += gp[2*H + h];
        go += gp[3*H + h];
    }
    gi += b_ih[h]       + b_hh[h];
    gf += b_ih[H + h]   + b_hh[H + h];
    gg += b_ih[2*H + h] + b_hh[2*H + h];
    go += b_ih[3*H + h] + b_hh[3*H + h];
    float ig = sigf(gi);
    float fg = sigf(gf);
    float gv = tanhf(gg);
    float og = sigf(go);
    float c  = fg * c0[b*H + h] + ig * gv;
    float ht = og * tanhf(c);
    out[OUT_HT + b*H + h] = ht;
    out[OUT_CT + b*H + h] = c;
    __half hh = __float2half(ht);
    g_ht_hi[b*H + h] = hh;
    g_ht_lo[b*H + h] = __float2half(ht - __half2float(hh));

    float acc = ht * ws_vec[h];
    acc += g_context[b*E + h]       * wh_vec[h];
    acc += g_context[b*E + h + 512] * wh_vec[h + 512];
    if (h < EMBD) acc += g_embed[b*EMBD + h] * wx_vec[h];
    #pragma unroll
    for (int o = 16; o > 0; o >>= 1) acc += __shfl_xor_sync(0xffffffffu, acc, o);
    if ((h & 31) == 0) red[h >> 5] = acc;
    __syncthreads();
    if (h == 0){
        float s = 0.f;
        for (int i = 0; i < 16; i++) s += red[i];
        g_pgen[b] = sigf(s);
    }
}

// ---------------- logits HMMA + fused softmax partials -------------------
#define LKC 32
#define LCH (H/LKC)
#define LRB 80
#define LH_ARR (64*LRB)
#define LW_ARR (128*LRB)
#define LSTG (2*LH_ARR + LW_ARR)

__global__ __launch_bounds__(256) void logits_mma(
        const float* __restrict__ vw, const float* __restrict__ vb){
    __shared__ char sm2[2*LSTG];
    const int tid  = threadIdx.x;
    const int lane = tid & 31, wid = tid >> 5;
    const int wm = wid & 3;
    const int wn = wid >> 2;
    const int n0 = blockIdx.x * 128;
    const uint32_t smb = smem_u32(sm2);

    auto loadA_cp = [&](int i){
        uint32_t stg = smb + (i&1)*LSTG;
        int k0 = i*LKC;
        #pragma unroll
        for (int it = 0; it < 2; it++){
            int f = tid + it*256;
            int digit = f >> 8, idx = f & 255;
            int r = idx >> 2, j = idx & 3;
            const __half* src = (digit ? g_ht_lo : g_ht_hi) + r*H + k0 + j*8;
            cp16(stg + digit*LH_ARR + r*LRB + j*16, src);
        }
        cp_commit();
    };

    const int br = tid >> 1;
    const int bkh = tid & 1;
    int rg = n0 + br; if (rg >= V) rg = V - 1;
    const float* Bbase = vw + (size_t)rg*H + bkh*16;

    float breg[16];
    auto loadB = [&](int k0){
        const float4* gp = (const float4*)(Bbase + k0);
        #pragma unroll
        for (int q = 0; q < 4; q++){
            float4 v = gp[q];
            breg[q*4+0] = v.x; breg[q*4+1] = v.y; breg[q*4+2] = v.z; breg[q*4+3] = v.w;
        }
    };
    auto storeB = [&](int stage){
        __half hb[16];
        #pragma unroll
        for (int q = 0; q < 16; q++) hb[q] = __float2half(breg[q]);
        uint32_t off = (stage&1)*LSTG + 2*LH_ARR + (uint32_t)br*LRB + bkh*32;
        *(uint4*)(sm2 + off)      = *(uint4*)&hb[0];
        *(uint4*)(sm2 + off + 16) = *(uint4*)&hb[8];
    };

    float c[8][4];
    #pragma unroll
    for (int j = 0; j < 8; j++)
        #pragma unroll
        for (int q = 0; q < 4; q++) c[j][q] = 0.f;

    loadA_cp(0);
    loadB(0);
    storeB(0);
    loadB(LKC);

    for (int i = 0; i < LCH; i++){
        cp_wait0();
        __syncthreads();
        if (i + 1 < LCH){
            loadA_cp(i+1);
            storeB(i+1);
            if (i + 2 < LCH) loadB((i+2)*LKC);
        }

        const uint32_t stg = smb + (i&1)*LSTG;
        const uint32_t A0 = stg, A1 = stg + LH_ARR, B0 = stg + 2*LH_ARR;

        #pragma unroll
        for (int kk = 0; kk < 2; kk++){
            uint32_t ah[4], al[4];
            {
                int row = wm*16 + (lane & 15);
                uint32_t off = (uint32_t)row*LRB + (lane >> 4)*16 + kk*32;
                ldsm4(ah, A0 + off);
                ldsm4(al, A1 + off);
            }
            #pragma unroll
            for (int p = 0; p < 4; p++){
                int row = wn*64 + p*16 + ((lane >> 4) & 1)*8 + (lane & 7);
                uint32_t off = (uint32_t)row*LRB + ((lane >> 3) & 1)*16 + kk*32;
                uint32_t rh[4];
                ldsm4(rh, B0 + off);
                mma_f16(c[2*p],   ah, rh[0], rh[1]);
                mma_f16(c[2*p],   al, rh[0], rh[1]);
                mma_f16(c[2*p+1], ah, rh[2], rh[3]);
                mma_f16(c[2*p+1], al, rh[2], rh[3]);
            }
        }
    }

    float lm[2] = {-1e30f, -1e30f}, ls[2] = {0.f, 0.f};
    #pragma unroll
    for (int j = 0; j < 8; j++)
        #pragma unroll
        for (int q = 0; q < 4; q++){
            int t2 = q >> 1;
            int m = wm*16 + (lane >> 2) + t2*8;
            int v = n0 + wn*64 + j*8 + (lane & 3)*2 + (q & 1);
            float x = -1e30f;
            if (v < V){
                x = c[j][q] + vb[v];
                g_logits[(size_t)m*V + v] = x;
            }
            online(lm[t2], ls[t2], x);
        }
    #pragma unroll
    for (int t2 = 0; t2 < 2; t2++){
        #pragma unroll
        for (int o = 1; o <= 2; o <<= 1){
            float mo = __shfl_xor_sync(0xffffffffu, lm[t2], o);
            float so = __shfl_xor_sync(0xffffffffu, ls[t2], o);
            online_merge(lm[t2], ls[t2], mo, so);
        }
    }
    __syncthreads();
    float* rm = (float*)sm2;
    float* rs = rm + 64;
    if (wn == 0 && (lane & 3) == 0){
        #pragma unroll
        for (int t2 = 0; t2 < 2; t2++){
            int r = wm*16 + (lane >> 2) + t2*8;
            rm[r] = lm[t2];
            rs[r] = ls[t2];
        }
    }
    __syncthreads();
    if (wn == 1 && (lane & 3) == 0){
        #pragma unroll
        for (int t2 = 0; t2 < 2; t2++){
            int r = wm*16 + (lane >> 2) + t2*8;
            float M = lm[t2], Sx = ls[t2];
            online_merge(M, Sx, rm[r], rs[r]);
            g_lmax[blockIdx.x][r] = M;
            g_lsum[blockIdx.x][r] = Sx;
        }
    }
}

// ---------------- vocab reduce -------------------------------------------
__global__ void vocab_reduce(){
    const int b = blockIdx.x, t = threadIdx.x;
    const int lane = t & 31, wrp = t >> 5;
    __shared__ float redm[8], reds[8];
    float m = -1e30f, s = 0.f;
    for (int blk = t; blk < NLBLK; blk += 256)
        online_merge(m, s, g_lmax[blk][b], g_lsum[blk][b]);
    #pragma unroll
    for (int o = 16; o > 0; o >>= 1){
        float mo = __shfl_xor_sync(0xffffffffu, m, o);
        float so = __shfl_xor_sync(0xffffffffu, s, o);
        online_merge(m, s, mo, so);
    }
    if (lane == 0){ redm[wrp] = m; reds[wrp] = s; }
    __syncthreads();
    if (t == 0){
        float M = redm[0], Sx = reds[0];
        for (int i = 1; i < 8; i++) online_merge(M, Sx, redm[i], reds[i]);
        g_vfin[b*2]     = M;
        g_vfin[b*2 + 1] = g_pgen[b] / Sx;
    }
}

// ---------------- vocab write (fully parallel) ---------------------------
#define VCHUNK 6283
__global__ void vocab_write(float* __restrict__ out){
    const int b = blockIdx.y;
    const float M = g_vfin[b*2], scale = g_vfin[b*2 + 1];
    const int v0 = blockIdx.x * VCHUNK;
    const int vend = min(v0 + VCHUNK, V);
    const float* row = g_logits + (size_t)b*V;
    for (int v = v0 + threadIdx.x; v < vend; v += 1024)
        out[(size_t)b*V + v] = __expf(row[v] - M) * scale;
}

// ---------------- copy-mechanism scatter ---------------------------------
__global__ void scatter_kernel(const int* __restrict__ enc_inputs,
                               float* __restrict__ out){
    const int idx = blockIdx.x*256 + threadIdx.x;
    if (idx >= MTOT) return;
    const int b = idx >> 11;
    const int tok = enc_inputs[idx];
    atomicAdd(&out[(size_t)b*V + tok], (1.f - g_pgen[b]) * g_attn[idx]);
}

// ---------------- launch --------------------------------------------------
extern "C" void kernel_launch(void* const* d_in, const int* in_sizes, int n_in,
                              void* d_out, int out_size) {
    const float* enc_out   = (const float*)d_in[0];
    const float* h0        = (const float*)d_in[1];
    const float* c0        = (const float*)d_in[2];
    const int*   dec_input = (const int*)  d_in[3];
    const int*   enc_inputs= (const int*)  d_in[4];
    const float* embed_tab = (const float*)d_in[5];
    const float* attn_wh_w = (const float*)d_in[6];
    const float* attn_wh_b = (const float*)d_in[7];
    const float* attn_ws_w = (const float*)d_in[8];
    const float* attn_ws_b = (const float*)d_in[9];
    const float* attn_v    = (const float*)d_in[10];
    const float* lstm_w_ih = (const float*)d_in[11];
    const float* lstm_w_hh = (const float*)d_in[12];
    const float* lstm_b_ih = (const float*)d_in[13];
    const float* lstm_b_hh = (const float*)d_in[14];
    const float* wh_vec    = (const float*)d_in[15];
    const float* ws_vec    = (const float*)d_in[16];
    const float* wx_vec    = (const float*)d_in[17];
    const float* v_w       = (const float*)d_in[18];
    const float* v_b       = (const float*)d_in[19];
    float* out = (float*)d_out;

    static bool attr_set = false;
    if (!attr_set){
        cudaFuncSetAttribute(energy_mma, cudaFuncAttributeMaxDynamicSharedMemorySize, EN_SMEM);
        attr_set = true;
    }

    // energy_mma kept as the 4th launch (ncu capture slot)
    conv_w_kernel<<<2048, 256>>>(attn_wh_w);
    wsapp_kernel<<<dim3(B, 64), 256>>>(h0, attn_ws_w, attn_ws_b, attn_wh_b);
    init_kernel<<<256, 256>>>(dec_input, embed_tab);
    energy_mma<<<dim3(H/NTILE, MTOT/MT), 256, EN_SMEM>>>(enc_out, attn_v);
    attn_softmax<<<B, 256>>>();
    context_kernel<<<dim3(B, 4, 4), 256>>>(enc_out);
    gates_gemm<<<dim3((4*H)/64, 8), 256>>>(h0, lstm_w_ih, lstm_w_hh);
    lstm_kernel<<<B, 512>>>(c0, lstm_b_ih, lstm_b_hh, wh_vec, ws_vec, wx_vec, out);
    logits_mma<<<NLBLK, 256>>>(v_w, v_b);
    vocab_reduce<<<B, 256>>>();
    vocab_write<<<dim3(8, B), 1024>>>(out);
    scatter_kernel<<<(MTOT + 255)/256, 256>>>(enc_inputs, out);
}

// round 17
// speedup vs baseline: 1.0607x; 1.0607x over previous
#include <cuda_runtime.h>
#include <cuda_fp16.h>
#include <math.h>
#include <stdint.h>

#define B 64
#define S 2048
#define E 1024
#define H 512
#define EMBD 256
#define V 50257
#define MTOT (B*S)
#define NLBLK ((V + 127)/128)      // 393 logits CTAs

#define OUT_HT ((size_t)B*V)
#define OUT_CT (OUT_HT + (size_t)B*H)

// ---------------- device scratch (no allocations allowed) ----------------
__device__ float g_ws_app[B*H];
__device__ float g_energy4[4][MTOT];
__device__ float g_attn[MTOT];
__device__ float g_context[B*E];
__device__ float g_embed[B*EMBD];
__device__ float g_gates8[8][B*4*H];
__device__ float g_logits[(size_t)B*V];
__device__ float g_pgen[B];
__device__ float g_lmax[NLBLK][B];
__device__ float g_lsum[NLBLK][B];

__device__ __half g_w_h[H*E];          // attn_wh_w fp16
__device__ __half g_ht_hi[B*H];
__device__ __half g_ht_lo[B*H];

__device__ __forceinline__ float sigf(float x){ return 1.f/(1.f+__expf(-x)); }
__device__ __forceinline__ float ftanh(float x){
    x = fminf(fmaxf(x, -15.f), 15.f);
    float e2 = __expf(2.f*x);
    return (e2 - 1.f) / (e2 + 1.f);
}
__device__ __forceinline__ void online(float& m, float& s, float x){
    if (x > m){ s = s*__expf(m - x) + 1.f; m = x; }
    else        s += __expf(x - m);
}
__device__ __forceinline__ void online_merge(float& m, float& s, float mo, float so){
    float M = fmaxf(m, mo);
    s = s*__expf(m - M) + so*__expf(mo - M);
    m = M;
}

// ======================= portable PTX helpers =============================
__device__ __forceinline__ uint32_t smem_u32(const void* p){
    uint32_t a;
    asm("{ .reg .u64 t; cvta.to.shared.u64 t, %1; cvt.u32.u64 %0, t; }" : "=r"(a) : "l"(p));
    return a;
}
__device__ __forceinline__ void cp16(uint32_t dst, const void* src){
    asm volatile("cp.async.cg.shared.global [%0], [%1], 16;" :: "r"(dst), "l"(src));
}
__device__ __forceinline__ void cp_commit(){ asm volatile("cp.async.commit_group;" ::: "memory"); }
__device__ __forceinline__ void cp_wait0(){ asm volatile("cp.async.wait_group 0;" ::: "memory"); }

__device__ __forceinline__ void ldsm4(uint32_t* r, uint32_t addr){
    asm volatile("ldmatrix.sync.aligned.m8n8.x4.shared.b16 {%0,%1,%2,%3}, [%4];"
        : "=r"(r[0]), "=r"(r[1]), "=r"(r[2]), "=r"(r[3]) : "r"(addr));
}
__device__ __forceinline__ void mma_f16(float* c, const uint32_t* a, uint32_t b0, uint32_t b1){
    asm volatile("mma.sync.aligned.m16n8k16.row.col.f32.f16.f16.f32 "
        "{%0,%1,%2,%3}, {%4,%5,%6,%7}, {%8,%9}, {%0,%1,%2,%3};"
        : "+f"(c[0]), "+f"(c[1]), "+f"(c[2]), "+f"(c[3])
        : "r"(a[0]), "r"(a[1]), "r"(a[2]), "r"(a[3]), "r"(b0), "r"(b1));
}

// ---------------- fused pre-kernel: conv_w | wsapp | init -----------------
// grid: [0,4096) wsapp (b = bid&63, ny = bid>>6)
//       [4096,6144) conv_w   [6144,6400) init
__global__ void pre_kernel(const float* __restrict__ attn_wh_w,
                           const float* __restrict__ h0,
                           const float* __restrict__ ws_w,
                           const float* __restrict__ ws_b,
                           const float* __restrict__ wh_b,
                           const int*   __restrict__ dec_input,
                           const float* __restrict__ table){
    __shared__ float hs[H];
    const int bid = blockIdx.x, tid = threadIdx.x;
    if (bid < 4096){
        const int b = bid & 63, ny = bid >> 6;
        for (int i = tid; i < H; i += 256) hs[i] = h0[b*H + i];
        __syncthreads();
        const int warp = tid >> 5, lane = tid & 31;
        const int n = ny*8 + warp;
        const float* wrow = ws_w + (size_t)n*H;
        float acc = 0.f;
        #pragma unroll
        for (int k = lane*4; k < H; k += 128){
            float4 w = *(const float4*)(wrow + k);
            acc += hs[k]*w.x + hs[k+1]*w.y + hs[k+2]*w.z + hs[k+3]*w.w;
        }
        #pragma unroll
        for (int o = 16; o > 0; o >>= 1) acc += __shfl_xor_sync(0xffffffffu, acc, o);
        if (lane == 0) g_ws_app[b*H + n] = acc + ws_b[n] + wh_b[n];
    } else if (bid < 6144){
        int i = (bid - 4096)*256 + tid;
        g_w_h[i] = __float2half(attn_wh_w[i]);
    } else {
        int i = (bid - 6144)*256 + tid;
        if (i < B*E) g_context[i] = 0.f;
        if (i < B*EMBD){
            int b = i >> 8, t = i & 255;
            g_embed[i] = table[(size_t)dec_input[b]*EMBD + t];
        }
    }
}

// ---------------- asymmetric fp16 2-product energy GEMM (R15, frozen) ----
#define MT 128
#define NTILE 128
#define KC 32
#define NCH (E/KC)
#define ROWB 80
#define ARRB (128*ROWB)
#define STG_BYTES (3*ARRB)
#define WS_OFF (2*STG_BYTES)
#define V_OFF  (WS_OFF + 512)
#define EN_SMEM (V_OFF + 512)

__global__ __launch_bounds__(256, 2) void energy_mma(
        const float* __restrict__ enc, const float* __restrict__ attn_v){
    extern __shared__ char sm[];
    const int tid  = threadIdx.x;
    const int lane = tid & 31, wid = tid >> 5;
    const int wm = wid & 3;
    const int wn = wid >> 2;
    const int n0 = blockIdx.x * NTILE;
    const int m0 = blockIdx.y * MT;
    const int b  = m0 >> 11;

    float* wsP = (float*)(sm + WS_OFF);
    float* vP  = (float*)(sm + V_OFF);
    for (int j = tid; j < NTILE; j += 256){
        wsP[j] = g_ws_app[b*H + n0 + j];
        vP[j]  = attn_v[n0 + j];
    }

    const uint32_t smb = smem_u32(sm);
    const __half* Bg = g_w_h + (size_t)n0*E;

    const int ar = tid >> 1;
    const int kh = tid & 1;
    const float* Abase = enc + (size_t)(m0 + ar)*E + kh*16;

    auto loadB = [&](int stage, int k0){
        uint32_t stg = smb + (stage&1)*STG_BYTES + 2*ARRB;
        #pragma unroll
        for (int it = 0; it < 2; it++){
            int f = tid + it*256;
            int r = f >> 2, j = f & 3;
            cp16(stg + r*ROWB + j*16, Bg + (size_t)r*E + k0 + j*8);
        }
        cp_commit();
    };

    float areg[16];
    auto loadA = [&](int k0){
        const float4* gp = (const float4*)(Abase + k0);
        #pragma unroll
        for (int q = 0; q < 4; q++){
            float4 v = gp[q];
            areg[q*4+0] = v.x; areg[q*4+1] = v.y; areg[q*4+2] = v.z; areg[q*4+3] = v.w;
        }
    };
    auto storeA = [&](int stage){
        uint32_t off0 = (stage&1)*STG_BYTES;
        __half hb[16], lb[16];
        #pragma unroll
        for (int q = 0; q < 16; q++){
            hb[q] = __float2half(areg[q]);
            lb[q] = __float2half(areg[q] - __half2float(hb[q]));
        }
        uint32_t off = off0 + (uint32_t)ar*ROWB + kh*32;
        *(uint4*)(sm + off)              = *(uint4*)&hb[0];
        *(uint4*)(sm + off + 16)         = *(uint4*)&hb[8];
        *(uint4*)(sm + ARRB + off)       = *(uint4*)&lb[0];
        *(uint4*)(sm + ARRB + off + 16)  = *(uint4*)&lb[8];
    };

    float c[2][8][4];
    #pragma unroll
    for (int t = 0; t < 2; t++)
        #pragma unroll
        for (int j = 0; j < 8; j++)
            #pragma unroll
            for (int q = 0; q < 4; q++) c[t][j][q] = 0.f;

    loadB(0, 0);
    loadA(0);
    storeA(0);
    loadA(KC);

    for (int i = 0; i < NCH; i++){
        cp_wait0();
        __syncthreads();
        if (i + 1 < NCH){
            loadB(i+1, (i+1)*KC);
            storeA(i+1);
            if (i + 2 < NCH) loadA((i+2)*KC);
        }

        const uint32_t stg = smb + (i&1)*STG_BYTES;
        const uint32_t A0 = stg, A1 = stg + ARRB, B0 = stg + 2*ARRB;

        #pragma unroll
        for (int kk = 0; kk < 2; kk++){
            uint32_t ah[2][4], al[2][4];
            #pragma unroll
            for (int t = 0; t < 2; t++){
                int row = wm*32 + t*16 + (lane & 15);
                uint32_t off = (uint32_t)row*ROWB + (lane >> 4)*16 + kk*32;
                ldsm4(ah[t], A0 + off);
                ldsm4(al[t], A1 + off);
            }
            #pragma unroll
            for (int p = 0; p < 4; p++){
                int row = wn*64 + p*16 + ((lane >> 4) & 1)*8 + (lane & 7);
                uint32_t off = (uint32_t)row*ROWB + ((lane >> 3) & 1)*16 + kk*32;
                uint32_t rh[4];
                ldsm4(rh, B0 + off);
                #pragma unroll
                for (int t = 0; t < 2; t++){
                    mma_f16(c[t][2*p],   ah[t], rh[0], rh[1]);
                    mma_f16(c[t][2*p],   al[t], rh[0], rh[1]);
                    mma_f16(c[t][2*p+1], ah[t], rh[2], rh[3]);
                    mma_f16(c[t][2*p+1], al[t], rh[2], rh[3]);
                }
            }
        }
    }

    float p4[4] = {0.f, 0.f, 0.f, 0.f};
    #pragma unroll
    for (int t = 0; t < 2; t++)
        #pragma unroll
        for (int j = 0; j < 8; j++)
            #pragma unroll
            for (int q = 0; q < 4; q++){
                int nloc = wn*64 + j*8 + (lane & 3)*2 + (q & 1);
                float x = c[t][j][q] + wsP[nloc];
                p4[t*2 + (q >> 1)] += ftanh(x) * vP[nloc];
            }
    #pragma unroll
    for (int q = 0; q < 4; q++){
        p4[q] += __shfl_xor_sync(0xffffffffu, p4[q], 1);
        p4[q] += __shfl_xor_sync(0xffffffffu, p4[q], 2);
    }
    __syncthreads();
    float* red = (float*)(sm);
    if ((lane & 3) == 0){
        int rloc = wm*32 + (lane >> 2);
        if (wn == 0){
            red[rloc]      = p4[0];
            red[rloc + 8]  = p4[1];
            red[rloc + 16] = p4[2];
            red[rloc + 24] = p4[3];
        }
    }
    __syncthreads();
    if (wn == 1 && (lane & 3) == 0){
        int rloc = wm*32 + (lane >> 2);
        g_energy4[blockIdx.x][m0 + rloc]      = red[rloc]      + p4[0];
        g_energy4[blockIdx.x][m0 + rloc + 8]  = red[rloc + 8]  + p4[1];
        g_energy4[blockIdx.x][m0 + rloc + 16] = red[rloc + 16] + p4[2];
        g_energy4[blockIdx.x][m0 + rloc + 24] = red[rloc + 24] + p4[3];
    }
}

// ---------------- softmax over S per batch -------------------------------
__global__ void attn_softmax(){
    const int b = blockIdx.x, t = threadIdx.x;
    __shared__ float red[8];
    float ev[8];
    float m = -1e30f;
    #pragma unroll
    for (int q = 0; q < 8; q++){
        int idx = b*S + q*256 + t;
        float v = g_energy4[0][idx] + g_energy4[1][idx] + g_energy4[2][idx] + g_energy4[3][idx];
        ev[q] = v;
        m = fmaxf(m, v);
    }
    #pragma unroll
    for (int o = 16; o > 0; o >>= 1) m = fmaxf(m, __shfl_xor_sync(0xffffffffu, m, o));
    if ((t & 31) == 0) red[t >> 5] = m;
    __syncthreads();
    if (t == 0){ float mm = red[0]; for (int i = 1; i < 8; i++) mm = fmaxf(mm, red[i]); red[0] = mm; }
    __syncthreads();
    m = red[0];
    __syncthreads();
    float s = 0.f;
    #pragma unroll
    for (int q = 0; q < 8; q++){ ev[q] = __expf(ev[q]-m); s += ev[q]; }
    #pragma unroll
    for (int o = 16; o > 0; o >>= 1) s += __shfl_xor_sync(0xffffffffu, s, o);
    if ((t & 31) == 0) red[t >> 5] = s;
    __syncthreads();
    if (t == 0){ float ss = 0.f; for (int i = 0; i < 8; i++) ss += red[i]; red[0] = ss; }
    __syncthreads();
    float inv = 1.f / red[0];
    #pragma unroll
    for (int q = 0; q < 8; q++) g_attn[b*S + q*256 + t] = ev[q] * inv;
}

// ---------------- context --------------------------------------------------
__global__ void context_kernel(const float* __restrict__ enc){
    const int b = blockIdx.x, ec = blockIdx.y, sc = blockIdx.z;
    __shared__ float a_s[512];
    const int t = threadIdx.x;
    for (int i = t; i < 512; i += 256) a_s[i] = g_attn[b*S + sc*512 + i];
    __syncthreads();
    const int e = ec*256 + t;
    const float* base = enc + ((size_t)b*S + sc*512)*E + e;
    float acc = 0.f;
    #pragma unroll 4
    for (int s = 0; s < 512; s++) acc = fmaf(a_s[s], base[(size_t)s*E], acc);
    atomicAdd(&g_context[b*E + e], acc);
}

// ---------------- LSTM gates GEMM (K-split x8) ---------------------------
__global__ __launch_bounds__(256) void gates_gemm(
        const float* __restrict__ h0,
        const float* __restrict__ w_ih,
        const float* __restrict__ w_hh){
    __shared__ float Xs[16][65];
    __shared__ float Ws[16][65];
    const int n0 = blockIdx.x * 64;
    const int ks = blockIdx.y;
    const int tid = threadIdx.x;
    const int tx = tid & 15, ty = tid >> 4;
    float acc[4][4];
    #pragma unroll
    for (int i = 0; i < 4; i++)
        #pragma unroll
        for (int j = 0; j < 4; j++) acc[i][j] = 0.f;

    for (int k0 = ks*224; k0 < (ks+1)*224; k0 += 16) {
        for (int i = tid; i < 64*16; i += 256){
            int m = i >> 4, kk = i & 15, k = k0 + kk;
            float xv;
            if (k < E)            xv = g_context[m*E + k];
            else if (k < E+EMBD)  xv = g_embed[m*EMBD + (k - E)];
            else                  xv = h0[m*H + (k - E - EMBD)];
            Xs[kk][m] = xv;
        }
        for (int i = tid; i < 64*16; i += 256){
            int nn = i >> 4, kk = i & 15, k = k0 + kk, n = n0 + nn;
            float wv = (k < E+EMBD) ? w_ih[(size_t)n*(E+EMBD) + k]
                                    : w_hh[(size_t)n*H + (k - E - EMBD)];
            Ws[kk][nn] = wv;
        }
        __syncthreads();
        #pragma unroll
        for (int kk = 0; kk < 16; kk++){
            float ra[4], rb[4];
            #pragma unroll
            for (int i = 0; i < 4; i++) ra[i] = Xs[kk][ty*4+i];
            #pragma unroll
            for (int j = 0; j < 4; j++) rb[j] = Ws[kk][tx*4+j];
            #pragma unroll
            for (int i = 0; i < 4; i++)
                #pragma unroll
                for (int j = 0; j < 4; j++) acc[i][j] = fmaf(ra[i], rb[j], acc[i][j]);
        }
        __syncthreads();
    }
    #pragma unroll
    for (int i = 0; i < 4; i++)
        #pragma unroll
        for (int j = 0; j < 4; j++){
            int m = ty*4+i, n = n0 + tx*4+j;
            g_gates8[ks][m*(4*H) + n] = acc[i][j];
        }
}

// ---------------- LSTM pointwise + p_gen (fused) -------------------------
__global__ void lstm_kernel(const float* __restrict__ c0,
                            const float* __restrict__ b_ih,
                            const float* __restrict__ b_hh,
                            const float* __restrict__ wh_vec,
                            const float* __restrict__ ws_vec,
                            const float* __restrict__ wx_vec,
                            float* __restrict__ out){
    __shared__ float red[16];
    const int b = blockIdx.x, h = threadIdx.x;
    const int base = b*(4*H);
    float gi = 0.f, gf = 0.f, gg = 0.f, go = 0.f;
    #pragma unroll
    for (int p = 0; p < 8; p++){
        const float* gp = g_gates8[p] + base;
        gi += gp[h];
        gf += gp[H + h];
        gg += gp[2*H + h];
        go += gp[3*H + h];
    }
    gi += b_ih[h]       + b_hh[h];
    gf += b_ih[H + h]   + b_hh[H + h];
    gg += b_ih[2*H + h] + b_hh[2*H + h];
    go += b_ih[3*H + h] + b_hh[3*H + h];
    float ig = sigf(gi);
    float fg = sigf(gf);
    float gv = tanhf(gg);
    float og = sigf(go);
    float c  = fg * c0[b*H + h] + ig * gv;
    float ht = og * tanhf(c);
    out[OUT_HT + b*H + h] = ht;
    out[OUT_CT + b*H + h] = c;
    __half hh = __float2half(ht);
    g_ht_hi[b*H + h] = hh;
    g_ht_lo[b*H + h] = __float2half(ht - __half2float(hh));

    float acc = ht * ws_vec[h];
    acc += g_context[b*E + h]       * wh_vec[h];
    acc += g_context[b*E + h + 512] * wh_vec[h + 512];
    if (h < EMBD) acc += g_embed[b*EMBD + h] * wx_vec[h];
    #pragma unroll
    for (int o = 16; o > 0; o >>= 1) acc += __shfl_xor_sync(0xffffffffu, acc, o);
    if ((h & 31) == 0) red[h >> 5] = acc;
    __syncthreads();
    if (h == 0){
        float s = 0.f;
        for (int i = 0; i < 16; i++) s += red[i];
        g_pgen[b] = sigf(s);
    }
}

// ---------------- logits HMMA + fused softmax partials -------------------
#define LKC 32
#define LCH (H/LKC)
#define LRB 80
#define LH_ARR (64*LRB)
#define LW_ARR (128*LRB)
#define LSTG (2*LH_ARR + LW_ARR)

__global__ __launch_bounds__(256) void logits_mma(
        const float* __restrict__ vw, const float* __restrict__ vb){
    __shared__ char sm2[2*LSTG];
    const int tid  = threadIdx.x;
    const int lane = tid & 31, wid = tid >> 5;
    const int wm = wid & 3;
    const int wn = wid >> 2;
    const int n0 = blockIdx.x * 128;
    const uint32_t smb = smem_u32(sm2);

    auto loadA_cp = [&](int i){
        uint32_t stg = smb + (i&1)*LSTG;
        int k0 = i*LKC;
        #pragma unroll
        for (int it = 0; it < 2; it++){
            int f = tid + it*256;
            int digit = f >> 8, idx = f & 255;
            int r = idx >> 2, j = idx & 3;
            const __half* src = (digit ? g_ht_lo : g_ht_hi) + r*H + k0 + j*8;
            cp16(stg + digit*LH_ARR + r*LRB + j*16, src);
        }
        cp_commit();
    };

    const int br = tid >> 1;
    const int bkh = tid & 1;
    int rg = n0 + br; if (rg >= V) rg = V - 1;
    const float* Bbase = vw + (size_t)rg*H + bkh*16;

    float breg[16];
    auto loadB = [&](int k0){
        const float4* gp = (const float4*)(Bbase + k0);
        #pragma unroll
        for (int q = 0; q < 4; q++){
            float4 v = gp[q];
            breg[q*4+0] = v.x; breg[q*4+1] = v.y; breg[q*4+2] = v.z; breg[q*4+3] = v.w;
        }
    };
    auto storeB = [&](int stage){
        __half hb[16];
        #pragma unroll
        for (int q = 0; q < 16; q++) hb[q] = __float2half(breg[q]);
        uint32_t off = (stage&1)*LSTG + 2*LH_ARR + (uint32_t)br*LRB + bkh*32;
        *(uint4*)(sm2 + off)      = *(uint4*)&hb[0];
        *(uint4*)(sm2 + off + 16) = *(uint4*)&hb[8];
    };

    float c[8][4];
    #pragma unroll
    for (int j = 0; j < 8; j++)
        #pragma unroll
        for (int q = 0; q < 4; q++) c[j][q] = 0.f;

    loadA_cp(0);
    loadB(0);
    storeB(0);
    loadB(LKC);

    for (int i = 0; i < LCH; i++){
        cp_wait0();
        __syncthreads();
        if (i + 1 < LCH){
            loadA_cp(i+1);
            storeB(i+1);
            if (i + 2 < LCH) loadB((i+2)*LKC);
        }

        const uint32_t stg = smb + (i&1)*LSTG;
        const uint32_t A0 = stg, A1 = stg + LH_ARR, B0 = stg + 2*LH_ARR;

        #pragma unroll
        for (int kk = 0; kk < 2; kk++){
            uint32_t ah[4], al[4];
            {
                int row = wm*16 + (lane & 15);
                uint32_t off = (uint32_t)row*LRB + (lane >> 4)*16 + kk*32;
                ldsm4(ah, A0 + off);
                ldsm4(al, A1 + off);
            }
            #pragma unroll
            for (int p = 0; p < 4; p++){
                int row = wn*64 + p*16 + ((lane >> 4) & 1)*8 + (lane & 7);
                uint32_t off = (uint32_t)row*LRB + ((lane >> 3) & 1)*16 + kk*32;
                uint32_t rh[4];
                ldsm4(rh, B0 + off);
                mma_f16(c[2*p],   ah, rh[0], rh[1]);
                mma_f16(c[2*p],   al, rh[0], rh[1]);
                mma_f16(c[2*p+1], ah, rh[2], rh[3]);
                mma_f16(c[2*p+1], al, rh[2], rh[3]);
            }
        }
    }

    float lm[2] = {-1e30f, -1e30f}, ls[2] = {0.f, 0.f};
    #pragma unroll
    for (int j = 0; j < 8; j++)
        #pragma unroll
        for (int q = 0; q < 4; q++){
            int t2 = q >> 1;
            int m = wm*16 + (lane >> 2) + t2*8;
            int v = n0 + wn*64 + j*8 + (lane & 3)*2 + (q & 1);
            float x = -1e30f;
            if (v < V){
                x = c[j][q] + vb[v];
                g_logits[(size_t)m*V + v] = x;
            }
            online(lm[t2], ls[t2], x);
        }
    #pragma unroll
    for (int t2 = 0; t2 < 2; t2++){
        #pragma unroll
        for (int o = 1; o <= 2; o <<= 1){
            float mo = __shfl_xor_sync(0xffffffffu, lm[t2], o);
            float so = __shfl_xor_sync(0xffffffffu, ls[t2], o);
            online_merge(lm[t2], ls[t2], mo, so);
        }
    }
    __syncthreads();
    float* rm = (float*)sm2;
    float* rs = rm + 64;
    if (wn == 0 && (lane & 3) == 0){
        #pragma unroll
        for (int t2 = 0; t2 < 2; t2++){
            int r = wm*16 + (lane >> 2) + t2*8;
            rm[r] = lm[t2];
            rs[r] = ls[t2];
        }
    }
    __syncthreads();
    if (wn == 1 && (lane & 3) == 0){
        #pragma unroll
        for (int t2 = 0; t2 < 2; t2++){
            int r = wm*16 + (lane >> 2) + t2*8;
            float M = lm[t2], Sx = ls[t2];
            online_merge(M, Sx, rm[r], rs[r]);
            g_lmax[blockIdx.x][r] = M;
            g_lsum[blockIdx.x][r] = Sx;
        }
    }
}

// ---------------- vocab write (redundant per-CTA reduce + write) ---------
#define VCHUNK 6283
__global__ void vocab_write(float* __restrict__ out){
    const int b = blockIdx.y, t = threadIdx.x;   // 1024 threads
    const int lane = t & 31, wrp = t >> 5;
    __shared__ float redm[32], reds[32], fin[2];

    // redundant reduce of 393 partials (cheap; removes a serialized kernel)
    float m = -1e30f, s = 0.f;
    for (int blk = t; blk < NLBLK; blk += 1024)
        online_merge(m, s, g_lmax[blk][b], g_lsum[blk][b]);
    #pragma unroll
    for (int o = 16; o > 0; o >>= 1){
        float mo = __shfl_xor_sync(0xffffffffu, m, o);
        float so = __shfl_xor_sync(0xffffffffu, s, o);
        online_merge(m, s, mo, so);
    }
    if (lane == 0){ redm[wrp] = m; reds[wrp] = s; }
    __syncthreads();
    if (t < 32){
        float mm = redm[t], ss = reds[t];
        #pragma unroll
        for (int o = 16; o > 0; o >>= 1){
            float mo = __shfl_xor_sync(0xffffffffu, mm, o);
            float so = __shfl_xor_sync(0xffffffffu, ss, o);
            online_merge(mm, ss, mo, so);
        }
        if (t == 0){ fin[0] = mm; fin[1] = g_pgen[b] / ss; }
    }
    __syncthreads();
    const float M = fin[0], scale = fin[1];
    const int v0 = blockIdx.x * VCHUNK;
    const int vend = min(v0 + VCHUNK, V);
    const float* row = g_logits + (size_t)b*V;
    for (int v = v0 + t; v < vend; v += 1024)
        out[(size_t)b*V + v] = __expf(row[v] - M) * scale;
}

// ---------------- copy-mechanism scatter ---------------------------------
__global__ void scatter_kernel(const int* __restrict__ enc_inputs,
                               float* __restrict__ out){
    const int idx = blockIdx.x*256 + threadIdx.x;
    if (idx >= MTOT) return;
    const int b = idx >> 11;
    const int tok = enc_inputs[idx];
    atomicAdd(&out[(size_t)b*V + tok], (1.f - g_pgen[b]) * g_attn[idx]);
}

// ---------------- launch --------------------------------------------------
extern "C" void kernel_launch(void* const* d_in, const int* in_sizes, int n_in,
                              void* d_out, int out_size) {
    const float* enc_out   = (const float*)d_in[0];
    const float* h0        = (const float*)d_in[1];
    const float* c0        = (const float*)d_in[2];
    const int*   dec_input = (const int*)  d_in[3];
    const int*   enc_inputs= (const int*)  d_in[4];
    const float* embed_tab = (const float*)d_in[5];
    const float* attn_wh_w = (const float*)d_in[6];
    const float* attn_wh_b = (const float*)d_in[7];
    const float* attn_ws_w = (const float*)d_in[8];
    const float* attn_ws_b = (const float*)d_in[9];
    const float* attn_v    = (const float*)d_in[10];
    const float* lstm_w_ih = (const float*)d_in[11];
    const float* lstm_w_hh = (const float*)d_in[12];
    const float* lstm_b_ih = (const float*)d_in[13];
    const float* lstm_b_hh = (const float*)d_in[14];
    const float* wh_vec    = (const float*)d_in[15];
    const float* ws_vec    = (const float*)d_in[16];
    const float* wx_vec    = (const float*)d_in[17];
    const float* v_w       = (const float*)d_in[18];
    const float* v_b       = (const float*)d_in[19];
    float* out = (float*)d_out;

    static bool attr_set = false;
    if (!attr_set){
        cudaFuncSetAttribute(energy_mma, cudaFuncAttributeMaxDynamicSharedMemorySize, EN_SMEM);
        attr_set = true;
    }

    pre_kernel<<<6400, 256>>>(attn_wh_w, h0, attn_ws_w, attn_ws_b, attn_wh_b,
                              dec_input, embed_tab);
    energy_mma<<<dim3(H/NTILE, MTOT/MT), 256, EN_SMEM>>>(enc_out, attn_v);
    attn_softmax<<<B, 256>>>();
    context_kernel<<<dim3(B, 4, 4), 256>>>(enc_out);
    gates_gemm<<<dim3((4*H)/64, 8), 256>>>(h0, lstm_w_ih, lstm_w_hh);
    lstm_kernel<<<B, 512>>>(c0, lstm_b_ih, lstm_b_hh, wh_vec, ws_vec, wx_vec, out);
    logits_mma<<<NLBLK, 256>>>(v_w, v_b);
    vocab_write<<<dim3(8, B), 1024>>>(out);
    scatter_kernel<<<(MTOT + 255)/256, 256>>>(enc_inputs, out);
}